// round 13
// baseline (speedup 1.0000x reference)
#include <cuda_runtime.h>
#include <cuda_fp16.h>
#include <cstdint>

static constexpr int NMAX = 100000;
static constexpr int EMAX = 1300000;
static constexpr int D_ = 64;

// Scratch (static device globals — no runtime allocation)
__device__ __align__(256) __half g_xnh[NMAX * D_];  // normalized input, fp16 (gather table)
__device__ __align__(256) float g_msg[NMAX * D_];   // scaled message (gather output, fp32)
__device__ __align__(256) float g_h[NMAX * D_];     // layer-0 output (relu'd)
__device__ __align__(256) float g_normx[NMAX];
__device__ int g_deg[NMAX + 1];     // g_deg[n] doubles as the scan total
__device__ int g_off[NMAX];
__device__ int g_cur[NMAX];
__device__ int g_csr[EMAX];

__device__ __forceinline__ float warp_allreduce_sum(float v) {
#pragma unroll
    for (int o = 16; o; o >>= 1) v += __shfl_xor_sync(0xffffffffu, v, o);
    return v;
}

// ---- packed f32x2 helpers (FFMA2 path: PTX-only, sm_100+) -----------------
__device__ __forceinline__ unsigned long long fma2(unsigned long long a,
                                                   unsigned long long b,
                                                   unsigned long long c) {
    unsigned long long d;
    asm("fma.rn.f32x2 %0, %1, %2, %3;" : "=l"(d) : "l"(a), "l"(b), "l"(c));
    return d;
}
__device__ __forceinline__ float2 unpack2(unsigned long long v) {
    float2 r;
    asm("mov.b64 {%0, %1}, %2;" : "=f"(r.x), "=f"(r.y) : "l"(v));
    return r;
}

// ---------------------------------------------------------------------------
// k_prep_hist: fused. Blocks [0, pb): xnh = fp16(l2norm(x)), normx = ||x||
// (one warp per node). Blocks [pb, pb+hb): degree histogram, 4 edges/thread,
// atomic return discarded (REDG, fire-and-forget).
// ---------------------------------------------------------------------------
__global__ void k_prep_hist(const float* __restrict__ x,
                            const int* __restrict__ dst,
                            int n, int E, int pb, int hb) {
    if ((int)blockIdx.x < pb) {
        int t = blockIdx.x * blockDim.x + threadIdx.x;
        int node = t >> 5, lane = t & 31;
        if (node >= n) return;
        float2 v = reinterpret_cast<const float2*>(x)[node * 32 + lane];
        float s = warp_allreduce_sum(v.x * v.x + v.y * v.y);
        float nrm = sqrtf(s);
        float inv = 1.0f / fmaxf(nrm, 1e-12f);
        reinterpret_cast<__half2*>(g_xnh)[node * 32 + lane] =
            __float22half2_rn(make_float2(v.x * inv, v.y * inv));
        if (lane == 0) g_normx[node] = nrm;
    } else {
        int t = ((int)blockIdx.x - pb) * blockDim.x + threadIdx.x;
        int S = hb * blockDim.x;
        int e0 = t, e1 = t + S, e2 = t + 2 * S, e3 = t + 3 * S;
        int d0 = (e0 < E) ? dst[e0] : -1;
        int d1 = (e1 < E) ? dst[e1] : -1;
        int d2 = (e2 < E) ? dst[e2] : -1;
        int d3 = (e3 < E) ? dst[e3] : -1;
        if (d0 >= 0) atomicAdd(&g_deg[d0], 1);   // return unused -> REDG
        if (d1 >= 0) atomicAdd(&g_deg[d1], 1);
        if (d2 >= 0) atomicAdd(&g_deg[d2], 1);
        if (d3 >= 0) atomicAdd(&g_deg[d3], 1);
    }
}

// Offset reservation: block-level scan, ONE global atomic per block (to g_deg[n]).
__global__ void k_resv(int n) {
    __shared__ int warp_sums[8];
    __shared__ int block_base;
    int v = blockIdx.x * blockDim.x + threadIdx.x;
    int lane = threadIdx.x & 31, w = threadIdx.x >> 5;
    int d = (v < n) ? g_deg[v] : 0;
    int incl = d;
#pragma unroll
    for (int o = 1; o < 32; o <<= 1) {
        int t = __shfl_up_sync(0xffffffffu, incl, o);
        if (lane >= o) incl += t;
    }
    if (lane == 31) warp_sums[w] = incl;
    __syncthreads();
    if (w == 0) {
        int s = (lane < 8) ? warp_sums[lane] : 0;
        int si = s;
#pragma unroll
        for (int o = 1; o < 8; o <<= 1) {
            int t = __shfl_up_sync(0xffffffffu, si, o);
            if (lane >= o) si += t;
        }
        int tot = __shfl_sync(0xffffffffu, si, 7);
        if (lane == 0) block_base = atomicAdd(&g_deg[n], tot);
        if (lane < 8) warp_sums[lane] = si - s;   // exclusive warp offsets
    }
    __syncthreads();
    if (v < n) {
        int o = block_base + warp_sums[w] + incl - d;
        g_off[v] = o;
        g_cur[v] = o;
    }
}

// k_fill: 4 edges/thread (strided batches). Loads first, then 4 INDEPENDENT
// return-atomics in flight (MLP=4 on the 318-cyc ATOMG), then STGs.
__global__ void k_fill(const int* __restrict__ src, const int* __restrict__ dst, int E) {
    int t = blockIdx.x * blockDim.x + threadIdx.x;
    int S = gridDim.x * blockDim.x;
    int e0 = t, e1 = t + S, e2 = t + 2 * S, e3 = t + 3 * S;
    int d0 = (e0 < E) ? dst[e0] : -1;
    int d1 = (e1 < E) ? dst[e1] : -1;
    int d2 = (e2 < E) ? dst[e2] : -1;
    int d3 = (e3 < E) ? dst[e3] : -1;
    int s0 = (e0 < E) ? src[e0] : 0;
    int s1 = (e1 < E) ? src[e1] : 0;
    int s2 = (e2 < E) ? src[e2] : 0;
    int s3 = (e3 < E) ? src[e3] : 0;
    int p0 = (d0 >= 0) ? atomicAdd(&g_cur[d0], 1) : 0;
    int p1 = (d1 >= 0) ? atomicAdd(&g_cur[d1], 1) : 0;
    int p2 = (d2 >= 0) ? atomicAdd(&g_cur[d2], 1) : 0;
    int p3 = (d3 >= 0) ? atomicAdd(&g_cur[d3], 1) : 0;
    if (d0 >= 0) g_csr[p0] = s0;
    if (d1 >= 0) g_csr[p1] = s1;
    if (d2 >= 0) g_csr[p2] = s2;
    if (d3 >= 0) g_csr[p3] = s3;
}

// ---------------------------------------------------------------------------
// k_gather: persistent grid-stride, one warp per node per iteration.
// Each warp handles ~10 nodes -> per-warp work = sum of ~10 degrees ->
// variance collapses (no block waits on one high-degree node).
// Rows fp16 (one 128B line per edge), accumulate fp32, MLP=8.
// ---------------------------------------------------------------------------
__global__ void k_gather(const float* __restrict__ scale_p, int n) {
    int gw = (blockIdx.x * blockDim.x + threadIdx.x) >> 5;
    int lane = threadIdx.x & 31;
    int nW = (gridDim.x * blockDim.x) >> 5;
    const __half2* xnu = reinterpret_cast<const __half2*>(g_xnh);
    const float scale = scale_p[0];
    for (int node = gw; node < n; node += nW) {
        float2 acc = __half22float2(xnu[node * 32 + lane]);
        int off = g_off[node], deg = g_deg[node];
        int j = 0;
        for (; j + 8 <= deg; j += 8) {             // MLP=8 independent row loads
            int s0 = g_csr[off + j],     s1 = g_csr[off + j + 1];
            int s2 = g_csr[off + j + 2], s3 = g_csr[off + j + 3];
            int s4 = g_csr[off + j + 4], s5 = g_csr[off + j + 5];
            int s6 = g_csr[off + j + 6], s7 = g_csr[off + j + 7];
            __half2 h0 = xnu[s0 * 32 + lane];
            __half2 h1 = xnu[s1 * 32 + lane];
            __half2 h2 = xnu[s2 * 32 + lane];
            __half2 h3 = xnu[s3 * 32 + lane];
            __half2 h4 = xnu[s4 * 32 + lane];
            __half2 h5 = xnu[s5 * 32 + lane];
            __half2 h6 = xnu[s6 * 32 + lane];
            __half2 h7 = xnu[s7 * 32 + lane];
            float2 f0 = __half22float2(h0), f1 = __half22float2(h1);
            float2 f2 = __half22float2(h2), f3 = __half22float2(h3);
            float2 f4 = __half22float2(h4), f5 = __half22float2(h5);
            float2 f6 = __half22float2(h6), f7 = __half22float2(h7);
            acc.x += ((f0.x + f1.x) + (f2.x + f3.x)) + ((f4.x + f5.x) + (f6.x + f7.x));
            acc.y += ((f0.y + f1.y) + (f2.y + f3.y)) + ((f4.y + f5.y) + (f6.y + f7.y));
        }
        for (; j + 2 <= deg; j += 2) {
            float2 f0 = __half22float2(xnu[g_csr[off + j] * 32 + lane]);
            float2 f1 = __half22float2(xnu[g_csr[off + j + 1] * 32 + lane]);
            acc.x += f0.x + f1.x;
            acc.y += f0.y + f1.y;
        }
        if (j < deg) {
            float2 f0 = __half22float2(xnu[g_csr[off + j] * 32 + lane]);
            acc.x += f0.x; acc.y += f0.y;
        }
        float ss = warp_allreduce_sum(acc.x * acc.x + acc.y * acc.y);
        float f = g_normx[node] * scale / fmaxf(sqrtf(ss), 1e-12f);
        reinterpret_cast<float2*>(g_msg)[node * 32 + lane] =
            make_float2(acc.x * f, acc.y * f);
    }
}

// ---------------------------------------------------------------------------
// k_update: dual GEMM + final l2norm (+relu / next-layer prep when FIRST).
// 64 nodes per 256-thread block, 8 nodes per warp (round-7 geometry).
//   out = msg @ Wl^T + bl + x @ Wr^T ; out = l2norm(out)
// GEMM uses packed fma.rn.f32x2 (2 MACs per instruction).
// ---------------------------------------------------------------------------
template <bool FIRST>
__global__ void k_update(const float* __restrict__ xin_param,
                         const float* __restrict__ Wl, const float* __restrict__ bl,
                         const float* __restrict__ Wr,
                         float* __restrict__ out, int n) {
    extern __shared__ float sm[];
    float* sWl  = sm;                  // 64 * 68
    float* sWr  = sm + 64 * 68;        // 64 * 68
    float* sMsg = sWr + 64 * 68;       // 64 * 64
    float* sX   = sMsg + 64 * 64;      // 64 * 64
    const int tid = threadIdx.x;
    const int base = blockIdx.x * 64;

    const float* xin = FIRST ? xin_param : g_h;

    for (int i = tid; i < 4096; i += 256) {
        int j = i >> 6, k = i & 63;
        sWl[j * 68 + k] = Wl[i];
        sWr[j * 68 + k] = Wr[i];
    }

    // Stage 1: copy msg + x rows to smem. 4 threads per node.
    {
        int nloc = tid >> 2, c = tid & 3;
        int node = base + nloc;
        int rnode = (node < n) ? node : (n - 1);
        const float4* mg = reinterpret_cast<const float4*>(g_msg + rnode * 64) + c;
        float4* mp = reinterpret_cast<float4*>(sMsg + nloc * 64) + c;
        mp[0]  = mg[0];  mp[4]  = mg[4];  mp[8]  = mg[8];  mp[12] = mg[12];
        const float4* xp = reinterpret_cast<const float4*>(xin + rnode * 64) + c;
        float4* sxp = reinterpret_cast<float4*>(sX + nloc * 64) + c;
        sxp[0]  = xp[0]; sxp[4]  = xp[4]; sxp[8]  = xp[8]; sxp[12] = xp[12];
    }
    __syncthreads();

    // Stage 2: GEMM. Warp w, nodes [w*8, w*8+8); lane -> outputs j, j+32.
    const int w = tid >> 5, lane = tid & 31;
    const int nb = w * 8;
    unsigned long long acc0[8], acc1[8];
#pragma unroll
    for (int m = 0; m < 8; m++) { acc0[m] = 0ull; acc1[m] = 0ull; }
    const ulonglong2* wl0p = reinterpret_cast<const ulonglong2*>(sWl + lane * 68);
    const ulonglong2* wl1p = reinterpret_cast<const ulonglong2*>(sWl + (lane + 32) * 68);
    const ulonglong2* wr0p = reinterpret_cast<const ulonglong2*>(sWr + lane * 68);
    const ulonglong2* wr1p = reinterpret_cast<const ulonglong2*>(sWr + (lane + 32) * 68);
#pragma unroll 2
    for (int k4 = 0; k4 < 16; k4++) {
        ulonglong2 wl0 = wl0p[k4], wl1 = wl1p[k4];
        ulonglong2 wr0 = wr0p[k4], wr1 = wr1p[k4];
#pragma unroll
        for (int m = 0; m < 8; m++) {
            ulonglong2 mg = reinterpret_cast<const ulonglong2*>(sMsg + (nb + m) * 64)[k4];
            ulonglong2 xv = reinterpret_cast<const ulonglong2*>(sX + (nb + m) * 64)[k4];
            acc0[m] = fma2(wl0.x, mg.x, acc0[m]);
            acc0[m] = fma2(wl0.y, mg.y, acc0[m]);
            acc0[m] = fma2(wr0.x, xv.x, acc0[m]);
            acc0[m] = fma2(wr0.y, xv.y, acc0[m]);
            acc1[m] = fma2(wl1.x, mg.x, acc1[m]);
            acc1[m] = fma2(wl1.y, mg.y, acc1[m]);
            acc1[m] = fma2(wr1.x, xv.x, acc1[m]);
            acc1[m] = fma2(wr1.y, xv.y, acc1[m]);
        }
    }

    float b0 = bl[lane], b1 = bl[lane + 32];
#pragma unroll
    for (int m = 0; m < 8; m++) {
        int node = base + nb + m;          // warp-uniform
        if (node < n) {
            float2 p0 = unpack2(acc0[m]), p1 = unpack2(acc1[m]);
            float o0 = p0.x + p0.y + b0, o1 = p1.x + p1.y + b1;
            float s = warp_allreduce_sum(o0 * o0 + o1 * o1);
            float inv = 1.0f / fmaxf(sqrtf(s), 1e-12f);
            o0 *= inv; o1 *= inv;
            if (FIRST) {
                // relu, then pre-compute next layer's xn (fp16) / normx.
                // Safe: layer-1 gather is a separate (later) launch.
                o0 = fmaxf(o0, 0.0f); o1 = fmaxf(o1, 0.0f);
                float s2 = warp_allreduce_sum(o0 * o0 + o1 * o1);
                float nrm2 = sqrtf(s2);
                float inv2 = 1.0f / fmaxf(nrm2, 1e-12f);
                g_h[node * 64 + lane]        = o0;
                g_h[node * 64 + lane + 32]   = o1;
                g_xnh[node * 64 + lane]      = __float2half_rn(o0 * inv2);
                g_xnh[node * 64 + lane + 32] = __float2half_rn(o1 * inv2);
                if (lane == 0) g_normx[node] = nrm2;
            } else {
                out[node * 64 + lane]      = o0;
                out[node * 64 + lane + 32] = o1;
            }
        }
    }
}

// ---------------------------------------------------------------------------
extern "C" void kernel_launch(void* const* d_in, const int* in_sizes, int n_in,
                              void* d_out, int out_size) {
    const float* x   = (const float*)d_in[0];
    const float* Wl0 = (const float*)d_in[1];
    const float* bl0 = (const float*)d_in[2];
    const float* Wr0 = (const float*)d_in[3];
    const float* sc0 = (const float*)d_in[4];
    const float* Wl1 = (const float*)d_in[5];
    const float* bl1 = (const float*)d_in[6];
    const float* Wr1 = (const float*)d_in[7];
    const float* sc1 = (const float*)d_in[8];
    const int*   ei  = (const int*)d_in[9];

    int n = in_sizes[0] / 64;
    int E = in_sizes[9] / 2;
    const int* src = ei;
    const int* dst = ei + E;
    float* out = (float*)d_out;

    void* deg_p;
    cudaGetSymbolAddress(&deg_p, g_deg);

    const int smem = (64 * 68 * 2 + 64 * 64 * 2) * (int)sizeof(float);  // 67584 B
    cudaFuncSetAttribute(k_update<true>,  cudaFuncAttributeMaxDynamicSharedMemorySize, smem);
    cudaFuncSetAttribute(k_update<false>, cudaFuncAttributeMaxDynamicSharedMemorySize, smem);

    int gn  = (n + 255) / 256;            // per-node, 1 thread
    int gw  = (n * 32 + 255) / 256;       // per-node, 1 warp (prep)
    int gu  = (n + 63) / 64;
    int pb  = gw;                          // prep blocks (1 warp/node)
    int hb  = (E + 1023) / 1024;           // hist blocks (4 edges/thread)
    int gf  = (E + 1023) / 1024;           // fill blocks (4 edges/thread)
    int gg  = 148 * 8;                     // persistent gather blocks

    // CSR build (used by both layers); g_deg[n] doubles as scan total -> 1 memset
    cudaMemsetAsync(deg_p, 0, (size_t)(n + 1) * sizeof(int));
    k_prep_hist<<<pb + hb, 256>>>(x, dst, n, E, pb, hb);
    k_resv<<<gn, 256>>>(n);
    k_fill<<<gf, 256>>>(src, dst, E);

    // Layer 0
    k_gather<<<gg, 256>>>(sc0, n);
    k_update<true><<<gu, 256, smem>>>(x, Wl0, bl0, Wr0, nullptr, n);
    // Layer 1 (input prep fused into k_update<true> epilogue)
    k_gather<<<gg, 256>>>(sc1, n);
    k_update<false><<<gu, 256, smem>>>(x, Wl1, bl1, Wr1, out, n);
}

// round 14
// speedup vs baseline: 1.5872x; 1.5872x over previous
#include <cuda_runtime.h>
#include <cuda_fp16.h>
#include <cstdint>

static constexpr int NMAX = 100000;
static constexpr int EMAX = 1300000;
static constexpr int D_ = 64;

// Scratch (static device globals — no runtime allocation)
__device__ __align__(256) __half g_xnh[NMAX * D_];   // normalized input, fp16 (gather table)
__device__ __align__(256) __half g_msgh[NMAX * D_];  // scaled message, fp16 (gather output)
__device__ __align__(256) __half g_hh[NMAX * D_];    // layer-0 output (relu'd), fp16
__device__ __align__(256) float g_normx[NMAX];
__device__ int g_deg[NMAX + 1];     // g_deg[n] doubles as the scan total
__device__ int g_off[NMAX];
__device__ int g_cur[NMAX];
__device__ int g_csr[EMAX];

__device__ __forceinline__ float warp_allreduce_sum(float v) {
#pragma unroll
    for (int o = 16; o; o >>= 1) v += __shfl_xor_sync(0xffffffffu, v, o);
    return v;
}

// m16n8k16 row.col f32.f16.f16.f32 MMA, D += A*B
__device__ __forceinline__ void mma16816(float* d, const uint32_t* a,
                                         uint32_t b0, uint32_t b1) {
    asm volatile(
        "mma.sync.aligned.m16n8k16.row.col.f32.f16.f16.f32 "
        "{%0,%1,%2,%3}, {%4,%5,%6,%7}, {%8,%9}, {%0,%1,%2,%3};"
        : "+f"(d[0]), "+f"(d[1]), "+f"(d[2]), "+f"(d[3])
        : "r"(a[0]), "r"(a[1]), "r"(a[2]), "r"(a[3]), "r"(b0), "r"(b1));
}

// ---------------------------------------------------------------------------
// k_prep_hist: fused. Blocks [0, pb): xnh = fp16(l2norm(x)), normx = ||x||
// (one warp per node). Blocks [pb, pb+hb): degree histogram, 4 edges/thread.
// ---------------------------------------------------------------------------
__global__ void k_prep_hist(const float* __restrict__ x,
                            const int* __restrict__ dst,
                            int n, int E, int pb, int hb) {
    if ((int)blockIdx.x < pb) {
        int t = blockIdx.x * blockDim.x + threadIdx.x;
        int node = t >> 5, lane = t & 31;
        if (node >= n) return;
        float2 v = reinterpret_cast<const float2*>(x)[node * 32 + lane];
        float s = warp_allreduce_sum(v.x * v.x + v.y * v.y);
        float nrm = sqrtf(s);
        float inv = 1.0f / fmaxf(nrm, 1e-12f);
        reinterpret_cast<__half2*>(g_xnh)[node * 32 + lane] =
            __float22half2_rn(make_float2(v.x * inv, v.y * inv));
        if (lane == 0) g_normx[node] = nrm;
    } else {
        int t = ((int)blockIdx.x - pb) * blockDim.x + threadIdx.x;
        int S = hb * blockDim.x;
        int e0 = t, e1 = t + S, e2 = t + 2 * S, e3 = t + 3 * S;
        int d0 = (e0 < E) ? dst[e0] : -1;
        int d1 = (e1 < E) ? dst[e1] : -1;
        int d2 = (e2 < E) ? dst[e2] : -1;
        int d3 = (e3 < E) ? dst[e3] : -1;
        if (d0 >= 0) atomicAdd(&g_deg[d0], 1);   // return unused -> REDG
        if (d1 >= 0) atomicAdd(&g_deg[d1], 1);
        if (d2 >= 0) atomicAdd(&g_deg[d2], 1);
        if (d3 >= 0) atomicAdd(&g_deg[d3], 1);
    }
}

// Offset reservation: block-level scan, ONE global atomic per block (to g_deg[n]).
__global__ void k_resv(int n) {
    __shared__ int warp_sums[8];
    __shared__ int block_base;
    int v = blockIdx.x * blockDim.x + threadIdx.x;
    int lane = threadIdx.x & 31, w = threadIdx.x >> 5;
    int d = (v < n) ? g_deg[v] : 0;
    int incl = d;
#pragma unroll
    for (int o = 1; o < 32; o <<= 1) {
        int t = __shfl_up_sync(0xffffffffu, incl, o);
        if (lane >= o) incl += t;
    }
    if (lane == 31) warp_sums[w] = incl;
    __syncthreads();
    if (w == 0) {
        int s = (lane < 8) ? warp_sums[lane] : 0;
        int si = s;
#pragma unroll
        for (int o = 1; o < 8; o <<= 1) {
            int t = __shfl_up_sync(0xffffffffu, si, o);
            if (lane >= o) si += t;
        }
        int tot = __shfl_sync(0xffffffffu, si, 7);
        if (lane == 0) block_base = atomicAdd(&g_deg[n], tot);
        if (lane < 8) warp_sums[lane] = si - s;   // exclusive warp offsets
    }
    __syncthreads();
    if (v < n) {
        int o = block_base + warp_sums[w] + incl - d;
        g_off[v] = o;
        g_cur[v] = o;
    }
}

// k_fill: 4 edges/thread (strided batches), MLP=4 on the return atomics.
__global__ void k_fill(const int* __restrict__ src, const int* __restrict__ dst, int E) {
    int t = blockIdx.x * blockDim.x + threadIdx.x;
    int S = gridDim.x * blockDim.x;
    int e0 = t, e1 = t + S, e2 = t + 2 * S, e3 = t + 3 * S;
    int d0 = (e0 < E) ? dst[e0] : -1;
    int d1 = (e1 < E) ? dst[e1] : -1;
    int d2 = (e2 < E) ? dst[e2] : -1;
    int d3 = (e3 < E) ? dst[e3] : -1;
    int s0 = (e0 < E) ? src[e0] : 0;
    int s1 = (e1 < E) ? src[e1] : 0;
    int s2 = (e2 < E) ? src[e2] : 0;
    int s3 = (e3 < E) ? src[e3] : 0;
    int p0 = (d0 >= 0) ? atomicAdd(&g_cur[d0], 1) : 0;
    int p1 = (d1 >= 0) ? atomicAdd(&g_cur[d1], 1) : 0;
    int p2 = (d2 >= 0) ? atomicAdd(&g_cur[d2], 1) : 0;
    int p3 = (d3 >= 0) ? atomicAdd(&g_cur[d3], 1) : 0;
    if (d0 >= 0) g_csr[p0] = s0;
    if (d1 >= 0) g_csr[p1] = s1;
    if (d2 >= 0) g_csr[p2] = s2;
    if (d3 >= 0) g_csr[p3] = s3;
}

// ---------------------------------------------------------------------------
// k_gather: one warp per node, fp16 rows, fp32 accumulate, MLP=8.
// Writes msg in fp16 (feeds the HMMA update directly).
// ---------------------------------------------------------------------------
__global__ void k_gather(const float* __restrict__ scale_p, int n) {
    int t = blockIdx.x * blockDim.x + threadIdx.x;
    int node = t >> 5, lane = t & 31;
    if (node >= n) return;
    const __half2* xnu = reinterpret_cast<const __half2*>(g_xnh);
    float2 acc = __half22float2(xnu[node * 32 + lane]);
    int off = g_off[node], deg = g_deg[node];
    int j = 0;
    for (; j + 8 <= deg; j += 8) {                 // MLP=8 independent row loads
        int s0 = g_csr[off + j],     s1 = g_csr[off + j + 1];
        int s2 = g_csr[off + j + 2], s3 = g_csr[off + j + 3];
        int s4 = g_csr[off + j + 4], s5 = g_csr[off + j + 5];
        int s6 = g_csr[off + j + 6], s7 = g_csr[off + j + 7];
        __half2 h0 = xnu[s0 * 32 + lane];
        __half2 h1 = xnu[s1 * 32 + lane];
        __half2 h2 = xnu[s2 * 32 + lane];
        __half2 h3 = xnu[s3 * 32 + lane];
        __half2 h4 = xnu[s4 * 32 + lane];
        __half2 h5 = xnu[s5 * 32 + lane];
        __half2 h6 = xnu[s6 * 32 + lane];
        __half2 h7 = xnu[s7 * 32 + lane];
        float2 f0 = __half22float2(h0), f1 = __half22float2(h1);
        float2 f2 = __half22float2(h2), f3 = __half22float2(h3);
        float2 f4 = __half22float2(h4), f5 = __half22float2(h5);
        float2 f6 = __half22float2(h6), f7 = __half22float2(h7);
        acc.x += ((f0.x + f1.x) + (f2.x + f3.x)) + ((f4.x + f5.x) + (f6.x + f7.x));
        acc.y += ((f0.y + f1.y) + (f2.y + f3.y)) + ((f4.y + f5.y) + (f6.y + f7.y));
    }
    for (; j + 2 <= deg; j += 2) {
        float2 f0 = __half22float2(xnu[g_csr[off + j] * 32 + lane]);
        float2 f1 = __half22float2(xnu[g_csr[off + j + 1] * 32 + lane]);
        acc.x += f0.x + f1.x;
        acc.y += f0.y + f1.y;
    }
    if (j < deg) {
        float2 f0 = __half22float2(xnu[g_csr[off + j] * 32 + lane]);
        acc.x += f0.x; acc.y += f0.y;
    }
    float ss = warp_allreduce_sum(acc.x * acc.x + acc.y * acc.y);
    float f = g_normx[node] * scale_p[0] / fmaxf(sqrtf(ss), 1e-12f);
    reinterpret_cast<__half2*>(g_msgh)[node * 32 + lane] =
        __float22half2_rn(make_float2(acc.x * f, acc.y * f));
}

// ---------------------------------------------------------------------------
// k_update (HMMA): 128 nodes / 256 threads per block.
// Single fused GEMM: D[128n x 64j] = A[128 x 128] * B[64 x 128]^T
//   A = [msg | x] fp16, B = [Wl | Wr] fp16 (row j).  fp32 accumulate.
// Row stride 136 halves -> fragment LDS.32 patterns are bank-conflict-free.
// Warp w owns node rows [16w,16w+16); per-node norms via intra-quad shfl.
// ---------------------------------------------------------------------------
static constexpr int AST = 136;  // half stride
template <bool FIRST>
__global__ void k_update(const float* __restrict__ xin,
                         const float* __restrict__ Wl, const float* __restrict__ bl,
                         const float* __restrict__ Wr,
                         float* __restrict__ out, int n) {
    extern __shared__ __half sh[];
    __half* sA = sh;                 // 128 x 136
    __half* sB = sh + 128 * AST;     // 64 x 136
    const int tid = threadIdx.x;
    const int base = blockIdx.x * 128;

    // B fill: [Wl | Wr] -> fp16
    for (int idx = tid; idx < 8192; idx += 256) {
        int j = idx >> 7, k = idx & 127;
        float v = (k < 64) ? Wl[j * 64 + k] : Wr[j * 64 + (k - 64)];
        sB[j * AST + k] = __float2half_rn(v);
    }
    // A fill: 2 threads per node row (c=0: msg fp16 copy; c=1: x)
    {
        int row = tid >> 1, c = tid & 1;
        int node = base + row;
        int rnode = (node < n) ? node : (n - 1);
        if (c == 0) {
            const uint4* s = reinterpret_cast<const uint4*>(g_msgh + rnode * 64);
            uint4* d = reinterpret_cast<uint4*>(sA + row * AST);
#pragma unroll
            for (int i = 0; i < 8; i++) d[i] = s[i];
        } else {
            if (FIRST) {
                const float4* s = reinterpret_cast<const float4*>(xin + rnode * 64);
                __half2* d = reinterpret_cast<__half2*>(sA + row * AST + 64);
#pragma unroll
                for (int i = 0; i < 16; i++) {
                    float4 f = s[i];
                    d[2 * i]     = __floats2half2_rn(f.x, f.y);
                    d[2 * i + 1] = __floats2half2_rn(f.z, f.w);
                }
            } else {
                const uint4* s = reinterpret_cast<const uint4*>(g_hh + rnode * 64);
                uint4* d = reinterpret_cast<uint4*>(sA + row * AST + 64);
#pragma unroll
                for (int i = 0; i < 8; i++) d[i] = s[i];
            }
        }
    }
    __syncthreads();

    const int w = tid >> 5, lane = tid & 31;
    const int gid = lane >> 2, tig = lane & 3;

    // A fragments for this warp's 16 rows, all 8 k-tiles, held in registers.
    const __half* A0 = sA + (w * 16 + gid) * AST;
    uint32_t a[8][4];
#pragma unroll
    for (int kt = 0; kt < 8; kt++) {
        int k0 = kt * 16 + 2 * tig;
        a[kt][0] = *reinterpret_cast<const uint32_t*>(A0 + k0);
        a[kt][1] = *reinterpret_cast<const uint32_t*>(A0 + 8 * AST + k0);
        a[kt][2] = *reinterpret_cast<const uint32_t*>(A0 + k0 + 8);
        a[kt][3] = *reinterpret_cast<const uint32_t*>(A0 + 8 * AST + k0 + 8);
    }

    float acc[8][4];
#pragma unroll
    for (int nt = 0; nt < 8; nt++)
#pragma unroll
        for (int i = 0; i < 4; i++) acc[nt][i] = 0.0f;

#pragma unroll
    for (int nt = 0; nt < 8; nt++) {
        const __half* B0 = sB + (nt * 8 + gid) * AST + 2 * tig;
#pragma unroll
        for (int kt = 0; kt < 8; kt++) {
            uint32_t b0 = *reinterpret_cast<const uint32_t*>(B0 + kt * 16);
            uint32_t b1 = *reinterpret_cast<const uint32_t*>(B0 + kt * 16 + 8);
            mma16816(acc[nt], a[kt], b0, b1);
        }
    }

    // Epilogue: bias, per-row l2norm (rows gid & gid+8 of this warp's block).
    float ss0 = 0.0f, ss1 = 0.0f;
#pragma unroll
    for (int nt = 0; nt < 8; nt++) {
        float2 b = *reinterpret_cast<const float2*>(bl + nt * 8 + 2 * tig);
        acc[nt][0] += b.x; acc[nt][1] += b.y;
        acc[nt][2] += b.x; acc[nt][3] += b.y;
        ss0 += acc[nt][0] * acc[nt][0] + acc[nt][1] * acc[nt][1];
        ss1 += acc[nt][2] * acc[nt][2] + acc[nt][3] * acc[nt][3];
    }
    ss0 += __shfl_xor_sync(0xffffffffu, ss0, 1);
    ss0 += __shfl_xor_sync(0xffffffffu, ss0, 2);
    ss1 += __shfl_xor_sync(0xffffffffu, ss1, 1);
    ss1 += __shfl_xor_sync(0xffffffffu, ss1, 2);
    float inv0 = 1.0f / fmaxf(sqrtf(ss0), 1e-12f);
    float inv1 = 1.0f / fmaxf(sqrtf(ss1), 1e-12f);

    int node0 = base + w * 16 + gid;
    int node1 = node0 + 8;
    if (FIRST) {
        // relu, then next layer's h (fp16), xn (fp16), normx
        float o[8][4];
        float s20 = 0.0f, s21 = 0.0f;
#pragma unroll
        for (int nt = 0; nt < 8; nt++) {
            o[nt][0] = fmaxf(acc[nt][0] * inv0, 0.0f);
            o[nt][1] = fmaxf(acc[nt][1] * inv0, 0.0f);
            o[nt][2] = fmaxf(acc[nt][2] * inv1, 0.0f);
            o[nt][3] = fmaxf(acc[nt][3] * inv1, 0.0f);
            s20 += o[nt][0] * o[nt][0] + o[nt][1] * o[nt][1];
            s21 += o[nt][2] * o[nt][2] + o[nt][3] * o[nt][3];
        }
        s20 += __shfl_xor_sync(0xffffffffu, s20, 1);
        s20 += __shfl_xor_sync(0xffffffffu, s20, 2);
        s21 += __shfl_xor_sync(0xffffffffu, s21, 1);
        s21 += __shfl_xor_sync(0xffffffffu, s21, 2);
        float nrm20 = sqrtf(s20), nrm21 = sqrtf(s21);
        float i20 = 1.0f / fmaxf(nrm20, 1e-12f);
        float i21 = 1.0f / fmaxf(nrm21, 1e-12f);
        __half2* hh = reinterpret_cast<__half2*>(g_hh);
        __half2* xh = reinterpret_cast<__half2*>(g_xnh);
        if (node0 < n) {
#pragma unroll
            for (int nt = 0; nt < 8; nt++) {
                int p = node0 * 32 + nt * 4 + tig;
                hh[p] = __floats2half2_rn(o[nt][0], o[nt][1]);
                xh[p] = __floats2half2_rn(o[nt][0] * i20, o[nt][1] * i20);
            }
            if (tig == 0) g_normx[node0] = nrm20;
        }
        if (node1 < n) {
#pragma unroll
            for (int nt = 0; nt < 8; nt++) {
                int p = node1 * 32 + nt * 4 + tig;
                hh[p] = __floats2half2_rn(o[nt][2], o[nt][3]);
                xh[p] = __floats2half2_rn(o[nt][2] * i21, o[nt][3] * i21);
            }
            if (tig == 0) g_normx[node1] = nrm21;
        }
    } else {
        if (node0 < n) {
#pragma unroll
            for (int nt = 0; nt < 8; nt++)
                *reinterpret_cast<float2*>(out + node0 * 64 + nt * 8 + 2 * tig) =
                    make_float2(acc[nt][0] * inv0, acc[nt][1] * inv0);
        }
        if (node1 < n) {
#pragma unroll
            for (int nt = 0; nt < 8; nt++)
                *reinterpret_cast<float2*>(out + node1 * 64 + nt * 8 + 2 * tig) =
                    make_float2(acc[nt][2] * inv1, acc[nt][3] * inv1);
        }
    }
}

// ---------------------------------------------------------------------------
extern "C" void kernel_launch(void* const* d_in, const int* in_sizes, int n_in,
                              void* d_out, int out_size) {
    const float* x   = (const float*)d_in[0];
    const float* Wl0 = (const float*)d_in[1];
    const float* bl0 = (const float*)d_in[2];
    const float* Wr0 = (const float*)d_in[3];
    const float* sc0 = (const float*)d_in[4];
    const float* Wl1 = (const float*)d_in[5];
    const float* bl1 = (const float*)d_in[6];
    const float* Wr1 = (const float*)d_in[7];
    const float* sc1 = (const float*)d_in[8];
    const int*   ei  = (const int*)d_in[9];

    int n = in_sizes[0] / 64;
    int E = in_sizes[9] / 2;
    const int* src = ei;
    const int* dst = ei + E;
    float* out = (float*)d_out;

    void* deg_p;
    cudaGetSymbolAddress(&deg_p, g_deg);

    const int smem = (128 * AST + 64 * AST) * (int)sizeof(__half);  // 52224 B
    cudaFuncSetAttribute(k_update<true>,  cudaFuncAttributeMaxDynamicSharedMemorySize, smem);
    cudaFuncSetAttribute(k_update<false>, cudaFuncAttributeMaxDynamicSharedMemorySize, smem);

    int gn  = (n + 255) / 256;            // per-node, 1 thread
    int gw  = (n * 32 + 255) / 256;       // per-node, 1 warp
    int gu  = (n + 127) / 128;
    int pb  = gw;                          // prep blocks (1 warp/node)
    int hb  = (E + 1023) / 1024;           // hist blocks (4 edges/thread)
    int gf  = (E + 1023) / 1024;           // fill blocks (4 edges/thread)

    // CSR build (used by both layers); g_deg[n] doubles as scan total -> 1 memset
    cudaMemsetAsync(deg_p, 0, (size_t)(n + 1) * sizeof(int));
    k_prep_hist<<<pb + hb, 256>>>(x, dst, n, E, pb, hb);
    k_resv<<<gn, 256>>>(n);
    k_fill<<<gf, 256>>>(src, dst, E);

    // Layer 0
    k_gather<<<gw, 256>>>(sc0, n);
    k_update<true><<<gu, 256, smem>>>(x, Wl0, bl0, Wr0, nullptr, n);
    // Layer 1 (input prep fused into k_update<true> epilogue)
    k_gather<<<gw, 256>>>(sc1, n);
    k_update<false><<<gu, 256, smem>>>(x, Wl1, bl1, Wr1, out, n);
}